// round 6
// baseline (speedup 1.0000x reference)
#include <cuda_runtime.h>

#define B_    8
#define N_    2048
#define EMB_  256
#define INNER_ 64
#define KNN_  16
#define NPTS_ (B_*N_)
#define MS    66    // mid row stride
#define HPD   68    // h/sim row stride
#define ST    260   // t row stride
#define GSZ   10512 // per-group smem floats

typedef unsigned long long ull;

__device__ __forceinline__ float2 unpk2(ull v) {
    float2 r; asm("mov.b64 {%0,%1}, %2;" : "=f"(r.x), "=f"(r.y) : "l"(v)); return r;
}
#define FMA2(acc, a, b) asm("fma.rn.f32x2 %0, %1, %2, %0;" : "+l"(acc) : "l"(a), "l"(b))

__device__ __forceinline__ void bar_g(int id) {
    asm volatile("bar.sync %0, 128;" :: "r"(id) : "memory");
}

// Scratch (device globals; no dynamic allocation allowed)
__device__ float g_qmk[NPTS_*INNER_];
__device__ float g_v  [NPTS_*INNER_];
__device__ int   g_idx[NPTS_*KNN_];
// pre-paired weights: pair p holds {w[2p][c], w[2p+1][c]}
__device__ __align__(16) float2 g_wqp[128*192];   // w_qkv
__device__ __align__(16) float2 g_w1p[32*256];    // w_att1
__device__ __align__(16) float2 g_w2p[128*64];    // w_att2
__device__ __align__(16) float2 g_wpp[32*64];     // w_pos2

// ---------------------------------------------------------------------------
__global__ __launch_bounds__(256) void prep_kernel(
    const float* __restrict__ wq, const float* __restrict__ w1,
    const float* __restrict__ w2, const float* __restrict__ wp)
{
    int i = blockIdx.x*256 + threadIdx.x;
    if (i < 24576) {
        int kp = i/192, c = i%192;
        g_wqp[i] = make_float2(wq[(2*kp)*192+c], wq[(2*kp+1)*192+c]);
    } else if (i < 32768) {
        int j = i - 24576; int kp = j>>8, c = j&255;
        g_w1p[j] = make_float2(w1[(2*kp)*256+c], w1[(2*kp+1)*256+c]);
    } else if (i < 40960) {
        int j = i - 32768; int kp = j>>6, c = j&63;
        g_w2p[j] = make_float2(w2[(2*kp)*64+c], w2[(2*kp+1)*64+c]);
    } else if (i < 43008) {
        int j = i - 40960; int kp = j>>6, c = j&63;
        g_wpp[j] = make_float2(wp[(2*kp)*64+c], wp[(2*kp+1)*64+c]);
    }
}

// ---------------------------------------------------------------------------
// qkv: 32 rows/block, 256 threads; thread tile = 8 rows x {q,k,v} of col cg.
// ---------------------------------------------------------------------------
__global__ __launch_bounds__(256) void qkv_kernel(const float* __restrict__ x)
{
    __shared__ float sx[32*EMB_];
    int r0 = blockIdx.x * 32;
    {
        const float4* xin = (const float4*)(x + (size_t)r0*EMB_);
        float4* sx4 = (float4*)sx;
        for (int i = threadIdx.x; i < 2048; i += 256) sx4[i] = xin[i];
    }
    __syncthreads();

    int cg = threadIdx.x & 63, rg = threadIdx.x >> 6;
    ull acc[8][3];
#pragma unroll
    for (int rr = 0; rr < 8; rr++)
#pragma unroll
        for (int cc = 0; cc < 3; cc++) acc[rr][cc] = 0ull;

    ull wc[3], wn[3];
#pragma unroll
    for (int cc = 0; cc < 3; cc++)
        wc[cc] = *(const ull*)&g_wqp[cg + 64*cc];

    for (int kp = 0; kp < 128; kp++) {
        if (kp < 127) {
#pragma unroll
            for (int cc = 0; cc < 3; cc++)
                wn[cc] = *(const ull*)&g_wqp[(kp+1)*192 + cg + 64*cc];
        }
#pragma unroll
        for (int rr = 0; rr < 8; rr++) {
            ull a = *(const ull*)&sx[(rg*8+rr)*EMB_ + 2*kp];
            FMA2(acc[rr][0], a, wc[0]);
            FMA2(acc[rr][1], a, wc[1]);
            FMA2(acc[rr][2], a, wc[2]);
        }
#pragma unroll
        for (int cc = 0; cc < 3; cc++) wc[cc] = wn[cc];
    }
#pragma unroll
    for (int rr = 0; rr < 8; rr++) {
        float2 sq = unpk2(acc[rr][0]);
        float2 sk = unpk2(acc[rr][1]);
        float2 sv = unpk2(acc[rr][2]);
        int row = r0 + rg*8 + rr;
        g_qmk[row*64 + cg] = (sq.x + sq.y) - (sk.x + sk.y);
        g_v  [row*64 + cg] = sv.x + sv.y;
    }
}

// ---------------------------------------------------------------------------
// kNN: 256 blocks x 256 threads; 64 queries/block, 4 threads/query.
// ---------------------------------------------------------------------------
__global__ __launch_bounds__(256) void knn_kernel(const float* __restrict__ pos)
{
    extern __shared__ float ksm[];
    float* sp = ksm;               // 6144
    float* sd = ksm + 6144;        // 4096
    int*   si = (int*)(ksm + 10240); // 4096

    int batch = blockIdx.x >> 5;
    int chunk = blockIdx.x & 31;
    const float* pb = pos + batch*N_*3;
    for (int e = threadIdx.x; e < N_*3; e += 256) sp[e] = pb[e];
    __syncthreads();

    int q = threadIdx.x >> 2;
    int s = threadIdx.x & 3;
    int qi = chunk*64 + q;
    float px = sp[qi*3+0], py = sp[qi*3+1], pz = sp[qi*3+2];

    float bd[KNN_]; int bi[KNN_];
#pragma unroll
    for (int t = 0; t < KNN_; t++) { bd[t] = 3.4e38f; bi[t] = 0; }

    int j0 = s * 512;
    for (int j = j0; j < j0 + 512; j++) {
        float dx = sp[j*3+0]-px, dy = sp[j*3+1]-py, dz = sp[j*3+2]-pz;
        float d2 = dx*dx + dy*dy + dz*dz;
        if (d2 < bd[KNN_-1]) {
            float cd = d2; int ci = j;
#pragma unroll
            for (int t = 0; t < KNN_; t++) {
                if (cd < bd[t]) {
                    float td = bd[t]; bd[t] = cd; cd = td;
                    int   ti = bi[t]; bi[t] = ci; ci = ti;
                }
            }
        }
    }
    int lb = (q*4 + s)*16;
#pragma unroll
    for (int t = 0; t < KNN_; t++) { sd[lb+t] = bd[t]; si[lb+t] = bi[t]; }
    __syncthreads();

    if (threadIdx.x < 64) {
        int qq = threadIdx.x;
        int p[4] = {0,0,0,0};
        int base = qq*64;
        int obase = (batch*N_ + chunk*64 + qq)*KNN_;
#pragma unroll
        for (int t = 0; t < KNN_; t++) {
            float best = sd[base + 0*16 + p[0]]; int bsel = 0;
            float c1 = sd[base + 1*16 + p[1]];
            if (c1 < best) { best = c1; bsel = 1; }
            float c2 = sd[base + 2*16 + p[2]];
            if (c2 < best) { best = c2; bsel = 2; }
            float c3 = sd[base + 3*16 + p[3]];
            if (c3 < best) { best = c3; bsel = 3; }
            g_idx[obase + t] = batch*N_ + si[base + bsel*16 + p[bsel]];
            p[bsel]++;
        }
    }
}

// ---------------------------------------------------------------------------
// Fused kernel: 2 points/block, 256 threads = 2 independent 128-thread
// warpgroups (1 point each, named barriers), 2 CTAs/SM.
// per-group smem (floats): sT 4160 | sP 4096 | sH 1088 | sVN 1024 |
//                          sRel 64 | sAgg 64 | sNbr 16  => GSZ=10512
// shared: sWPp 4096 | sWP1 192 | sBp1 64 | sBp2 64 | sBa1 256 | sBa2 64
// ---------------------------------------------------------------------------
#define SMEM_FUSED_FLOATS (2*GSZ + 4096 + 192 + 64 + 64 + 256 + 64)

__global__ __launch_bounds__(256, 2) void fused_kernel(
    const float* __restrict__ pos,
    const float* __restrict__ w_pos1, const float* __restrict__ b_pos1,
    const float* __restrict__ b_pos2,
    const float* __restrict__ b_att1, const float* __restrict__ b_att2,
    const float* __restrict__ w_out,  const float* __restrict__ b_out,
    float* __restrict__ out)
{
    extern __shared__ float sm[];
    float* sWPp = sm + 2*GSZ;            // 4096
    float* sWP1 = sWPp + 4096;           // 192
    float* sBp1 = sWP1 + 192;            // 64
    float* sBp2 = sBp1 + 64;             // 64
    float* sBa1 = sBp2 + 64;             // 256
    float* sBa2 = sBa1 + 256;            // 64

    const int tid  = threadIdx.x;
    const int g    = tid >> 7;           // warpgroup 0/1
    const int tl   = tid & 127;          // lane within group
    const int bid  = g + 1;              // named barrier id
    const int gp   = blockIdx.x * 2 + g; // global point

    float* GB   = sm + g*GSZ;
    float* sT   = GB;                    // mid (stride 66) then t (stride 260)
    float* sP   = GB + 4160;             // split-K partials (4x1024)
    float* sH   = GB + 8256;             // stride 68
    float* sVN  = GB + 9344;             // stride 64
    float* sRel = GB + 10368;            // 16x4
    float* sAgg = GB + 10432;            // 64
    int*   sNbr = (int*)(GB + 10496);    // 16

    // ---- Phase 0: block-wide weight staging + per-group neighbors ----
    {
        float4* d2 = (float4*)sWPp;  const float4* s2 = (const float4*)g_wpp;
        for (int i = tid; i < 1024; i += 256) d2[i] = s2[i];
    }
    if (tid < 192) sWP1[tid] = w_pos1[tid];
    if (tid < 64) {
        sBp1[tid] = b_pos1[tid];
        sBp2[tid] = b_pos2[tid];
        sBa2[tid] = b_att2[tid];
    }
    sBa1[tid] = b_att1[tid];
    if (tl < 16) {
        int nbr = g_idx[gp*KNN_ + tl];
        sNbr[tl] = nbr;
        sRel[tl*4+0] = pos[nbr*3+0] - pos[gp*3+0];
        sRel[tl*4+1] = pos[nbr*3+1] - pos[gp*3+1];
        sRel[tl*4+2] = pos[nbr*3+2] - pos[gp*3+2];
    }
    __syncthreads();   // once: weights visible to both groups

    // ---- Phase 1: mid = relu(rel @ wp1 + bp1), 16x64 -> sT stride MS ----
#pragma unroll
    for (int i = 0; i < 8; i++) {
        int e = tl + i*128;
        int r = e >> 6, c = e & 63;
        float a = sRel[r*4+0]*sWP1[c] + sRel[r*4+1]*sWP1[64+c]
                + sRel[r*4+2]*sWP1[128+c] + sBp1[c];
        sT[r*MS + c] = fmaxf(a, 0.f);
    }
    bar_g(bid);

    // ---- Phase 2: rpe = mid @ wp2 + bp2; h = qmk[nbr]+rpe; vn = v[nbr]+rpe ----
    {
        int cg = tl & 31, rg = tl >> 5;   // rg 0..3 -> 4 rows
        int r0v = rg * 4;
        ull acc[4][2];
#pragma unroll
        for (int rr = 0; rr < 4; rr++) { acc[rr][0] = 0ull; acc[rr][1] = 0ull; }
#pragma unroll 4
        for (int kp = 0; kp < 32; kp++) {
            ull w0 = *(const ull*)&sWPp[(kp*64 + cg)*2];
            ull w1 = *(const ull*)&sWPp[(kp*64 + cg + 32)*2];
#pragma unroll
            for (int rr = 0; rr < 4; rr++) {
                ull a = *(const ull*)&sT[(r0v+rr)*MS + 2*kp];
                FMA2(acc[rr][0], a, w0);
                FMA2(acc[rr][1], a, w1);
            }
        }
#pragma unroll
        for (int rr = 0; rr < 4; rr++) {
            int r = r0v + rr;
            int nbr = sNbr[r];
#pragma unroll
            for (int cc = 0; cc < 2; cc++) {
                int col = cg + 32*cc;
                float2 s = unpk2(acc[rr][cc]);
                float rpe = s.x + s.y + sBp2[col];
                sH [r*HPD + col] = g_qmk[nbr*64 + col] + rpe;
                sVN[r*64  + col] = g_v  [nbr*64 + col] + rpe;
            }
        }
    }
    bar_g(bid);

    // ---- Phase 3: t = relu(h @ w_att1 + b_att1), 16x256 -> sT stride ST ----
    {
        int cg = tl & 63, rg = tl >> 6;   // rg 0..1 -> 8 rows
        int r0v = rg * 8;
        ull acc[8][4];
#pragma unroll
        for (int rr = 0; rr < 8; rr++)
#pragma unroll
            for (int cc = 0; cc < 4; cc++) acc[rr][cc] = 0ull;

        ull wc[4], wn[4];
#pragma unroll
        for (int cc = 0; cc < 4; cc++)
            wc[cc] = *(const ull*)&g_w1p[cg + 64*cc];

        for (int kp = 0; kp < 32; kp++) {
            if (kp < 31) {
#pragma unroll
                for (int cc = 0; cc < 4; cc++)
                    wn[cc] = *(const ull*)&g_w1p[(kp+1)*256 + cg + 64*cc];
            }
#pragma unroll
            for (int rr = 0; rr < 8; rr++) {
                ull a = *(const ull*)&sH[(r0v+rr)*HPD + 2*kp];
                FMA2(acc[rr][0], a, wc[0]);
                FMA2(acc[rr][1], a, wc[1]);
                FMA2(acc[rr][2], a, wc[2]);
                FMA2(acc[rr][3], a, wc[3]);
            }
#pragma unroll
            for (int cc = 0; cc < 4; cc++) wc[cc] = wn[cc];
        }
#pragma unroll
        for (int rr = 0; rr < 8; rr++)
#pragma unroll
            for (int cc = 0; cc < 4; cc++) {
                int col = cg + 64*cc;
                float2 s = unpk2(acc[rr][cc]);
                sT[(r0v+rr)*ST + col] = fmaxf(s.x + s.y + sBa1[col], 0.f);
            }
    }
    bar_g(bid);

    // ---- Phase 4: sim = t @ w_att2 + b_att2 (split-K x4) -> sP -> sH ----
    {
        int sp = tl >> 5;                 // 0..3 k-split
        int t2 = tl & 31;
        int cg = t2 & 15, rg = t2 >> 4;   // rg 0..1 -> 8 rows
        int r0v = rg * 8;
        ull acc[8][4];
#pragma unroll
        for (int rr = 0; rr < 8; rr++)
#pragma unroll
            for (int cc = 0; cc < 4; cc++) acc[rr][cc] = 0ull;

        int kbase = sp * 32;
        ull wc[4], wn[4];
#pragma unroll
        for (int cc = 0; cc < 4; cc++)
            wc[cc] = *(const ull*)&g_w2p[kbase*64 + cg + 16*cc];

        for (int j = 0; j < 32; j++) {
            int kp = kbase + j;
            if (j < 31) {
#pragma unroll
                for (int cc = 0; cc < 4; cc++)
                    wn[cc] = *(const ull*)&g_w2p[(kp+1)*64 + cg + 16*cc];
            }
#pragma unroll
            for (int rr = 0; rr < 8; rr++) {
                ull a = *(const ull*)&sT[(r0v+rr)*ST + 2*kp];
                FMA2(acc[rr][0], a, wc[0]);
                FMA2(acc[rr][1], a, wc[1]);
                FMA2(acc[rr][2], a, wc[2]);
                FMA2(acc[rr][3], a, wc[3]);
            }
#pragma unroll
            for (int cc = 0; cc < 4; cc++) wc[cc] = wn[cc];
        }
#pragma unroll
        for (int rr = 0; rr < 8; rr++)
#pragma unroll
            for (int cc = 0; cc < 4; cc++) {
                float2 s = unpk2(acc[rr][cc]);
                sP[sp*1024 + (r0v+rr)*64 + cg + 16*cc] = s.x + s.y;
            }
    }
    bar_g(bid);
#pragma unroll
    for (int i = 0; i < 8; i++) {
        int e = tl + i*128;
        int r = e >> 6, col = e & 63;
        float sim = sP[e] + sP[1024+e] + sP[2048+e] + sP[3072+e] + sBa2[col];
        sH[r*HPD + col] = sim;
    }
    bar_g(bid);

    // ---- Phase 5: softmax over 64 channels per row (8 threads/row) ----
    {
        int row = tl >> 3, q = tl & 7;
        float* hrow = &sH[row*HPD + q*8];
        float mx = -3.4e38f;
#pragma unroll
        for (int i = 0; i < 8; i++) mx = fmaxf(mx, hrow[i]);
        mx = fmaxf(mx, __shfl_xor_sync(0xffffffffu, mx, 1));
        mx = fmaxf(mx, __shfl_xor_sync(0xffffffffu, mx, 2));
        mx = fmaxf(mx, __shfl_xor_sync(0xffffffffu, mx, 4));
        float ev[8];
        float s = 0.f;
#pragma unroll
        for (int i = 0; i < 8; i++) { ev[i] = __expf(hrow[i] - mx); s += ev[i]; }
        s += __shfl_xor_sync(0xffffffffu, s, 1);
        s += __shfl_xor_sync(0xffffffffu, s, 2);
        s += __shfl_xor_sync(0xffffffffu, s, 4);
        float inv = 1.f / s;
#pragma unroll
        for (int i = 0; i < 8; i++) hrow[i] = ev[i] * inv;
    }
    bar_g(bid);

    // ---- Phase 6: channel norm over 16 neighbors + aggregate ----
    if (tl < 64) {
        int cc = tl;
        float a[16];
        float s2 = 0.f;
#pragma unroll
        for (int j = 0; j < 16; j++) {
            a[j] = sH[j*HPD + cc];
            s2 += a[j]*a[j];
        }
        float inv = 1.f / fmaxf(sqrtf(s2), 1e-12f);
        float agg = 0.f;
#pragma unroll
        for (int j = 0; j < 16; j++)
            agg += a[j] * sVN[j*64 + cc];
        sAgg[cc] = agg * inv;
    }
    bar_g(bid);

    // ---- Phase 7: out = agg @ w_out + b_out (2 cols per thread) ----
    {
        int c0 = tl, c1 = tl + 128;
        float acc0 = b_out[c0], acc1 = b_out[c1];
#pragma unroll 4
        for (int c = 0; c < 64; c++) {
            float av = sAgg[c];
            acc0 += av * w_out[c*256 + c0];
            acc1 += av * w_out[c*256 + c1];
        }
        out[gp*256 + c0] = acc0;
        out[gp*256 + c1] = acc1;
    }
}

// ---------------------------------------------------------------------------
extern "C" void kernel_launch(void* const* d_in, const int* in_sizes, int n_in,
                              void* d_out, int out_size)
{
    const float* x      = (const float*)d_in[0];
    const float* pos    = (const float*)d_in[1];
    const float* w_qkv  = (const float*)d_in[2];
    const float* w_pos1 = (const float*)d_in[3];
    const float* b_pos1 = (const float*)d_in[4];
    const float* w_pos2 = (const float*)d_in[5];
    const float* b_pos2 = (const float*)d_in[6];
    const float* w_att1 = (const float*)d_in[7];
    const float* b_att1 = (const float*)d_in[8];
    const float* w_att2 = (const float*)d_in[9];
    const float* b_att2 = (const float*)d_in[10];
    const float* w_out  = (const float*)d_in[11];
    const float* b_out  = (const float*)d_in[12];
    float* out = (float*)d_out;

    (void)in_sizes; (void)n_in; (void)out_size;

    const int smem_fused = SMEM_FUSED_FLOATS * 4;
    cudaFuncSetAttribute(fused_kernel,
                         cudaFuncAttributeMaxDynamicSharedMemorySize, smem_fused);
    const int smem_knn = (6144 + 4096 + 4096) * 4;
    cudaFuncSetAttribute(knn_kernel,
                         cudaFuncAttributeMaxDynamicSharedMemorySize, smem_knn);

    prep_kernel<<<168, 256>>>(w_qkv, w_att1, w_att2, w_pos2);
    qkv_kernel<<<NPTS_/32, 256>>>(x);
    knn_kernel<<<256, 256, smem_knn>>>(pos);
    fused_kernel<<<NPTS_/2, 256, smem_fused>>>(
        pos, w_pos1, b_pos1, b_pos2, b_att1, b_att2, w_out, b_out, out);
}

// round 8
// speedup vs baseline: 1.6764x; 1.6764x over previous
#include <cuda_runtime.h>
#include <cuda_bf16.h>

#define B_    8
#define N_    2048
#define EMB_  256
#define KNN_  16
#define NPTS_ (B_*N_)

typedef unsigned long long ull;
typedef unsigned int u32;

__device__ __forceinline__ float2 unpk2(ull v) {
    float2 r; asm("mov.b64 {%0,%1}, %2;" : "=f"(r.x), "=f"(r.y) : "l"(v)); return r;
}
#define FMA2(acc, a, b) asm("fma.rn.f32x2 %0, %1, %2, %0;" : "+l"(acc) : "l"(a), "l"(b))

// bf16 hi/lo split packers (lower col -> low 16 bits)
__device__ __forceinline__ u32 pack_hi(float v0, float v1) {
    __nv_bfloat162 h = __floats2bfloat162_rn(v0, v1);
    return *(u32*)&h;
}
__device__ __forceinline__ u32 pack_lo(float v0, float v1) {
    __nv_bfloat16 h0 = __float2bfloat16(v0), h1 = __float2bfloat16(v1);
    __nv_bfloat162 l = __floats2bfloat162_rn(v0 - __bfloat162float(h0),
                                             v1 - __bfloat162float(h1));
    return *(u32*)&l;
}

// m16n8k16 bf16 mma, f32 accum (HMMA path, legal on compute_103)
__device__ __forceinline__ void mma_bf16(float d[4], const u32 a[4], u32 b0, u32 b1) {
    asm volatile("mma.sync.aligned.m16n8k16.row.col.f32.bf16.bf16.f32 "
        "{%0,%1,%2,%3}, {%4,%5,%6,%7}, {%8,%9}, {%0,%1,%2,%3};"
        : "+f"(d[0]), "+f"(d[1]), "+f"(d[2]), "+f"(d[3])
        : "r"(a[0]), "r"(a[1]), "r"(a[2]), "r"(a[3]), "r"(b0), "r"(b1));
}

// ---- Scratch (device globals) ----
__device__ float g_qmk[NPTS_*64];
__device__ float g_v  [NPTS_*64];
__device__ int   g_idx[NPTS_*KNN_];
__device__ __align__(16) float2 g_wqp[128*192];   // qkv weights paired
// B-fragment-ordered weights, bf16 hi half then lo half:
__device__ __align__(16) u32 g_w1f[16384];        // w_att1 [kt4][nt32][lane][b2] x2
__device__ __align__(16) u32 g_w2f[16384];        // w_att2 [kt16][nt8][lane][b2] x2
__device__ __align__(16) u32 g_wpf[4096];         // w_pos2 [kt4][nt8][lane][b2] x2

// ---------------------------------------------------------------------------
__global__ __launch_bounds__(256) void prep_kernel(
    const float* __restrict__ wq, const float* __restrict__ w1,
    const float* __restrict__ w2, const float* __restrict__ wp)
{
    int i = blockIdx.x*256 + threadIdx.x;
    if (i < 24576) {
        int kp = i/192, c = i%192;
        g_wqp[i] = make_float2(wq[(2*kp)*192+c], wq[(2*kp+1)*192+c]);
    } else if (i < 28672) {
        int j = i - 24576;               // wp2 frags, 4096 u32
        int half = j >> 11, j2 = j & 2047;
        int b = j2 & 1, lane = (j2 >> 1) & 31, nt = (j2 >> 6) & 7, kt = j2 >> 9;
        int tig = lane & 3, g = lane >> 2;
        int k0 = kt*16 + tig*2 + 8*b, n = nt*8 + g;
        float v0 = wp[k0*64 + n], v1 = wp[(k0+1)*64 + n];
        g_wpf[j] = half ? pack_lo(v0, v1) : pack_hi(v0, v1);
    } else if (i < 45056) {
        int j = i - 28672;               // w1 frags, 16384 u32
        int half = j >> 13, j2 = j & 8191;
        int b = j2 & 1, lane = (j2 >> 1) & 31, nt = (j2 >> 6) & 31, kt = j2 >> 11;
        int tig = lane & 3, g = lane >> 2;
        int k0 = kt*16 + tig*2 + 8*b, n = nt*8 + g;
        float v0 = w1[k0*256 + n], v1 = w1[(k0+1)*256 + n];
        g_w1f[j] = half ? pack_lo(v0, v1) : pack_hi(v0, v1);
    } else if (i < 61440) {
        int j = i - 45056;               // w2 frags, 16384 u32
        int half = j >> 13, j2 = j & 8191;
        int b = j2 & 1, lane = (j2 >> 1) & 31, nt = (j2 >> 6) & 7, kt = j2 >> 9;
        int tig = lane & 3, g = lane >> 2;
        int k0 = kt*16 + tig*2 + 8*b, n = nt*8 + g;
        float v0 = w2[k0*64 + n], v1 = w2[(k0+1)*64 + n];
        g_w2f[j] = half ? pack_lo(v0, v1) : pack_hi(v0, v1);
    }
}

// ---------------------------------------------------------------------------
// qkv: unchanged (register-tiled f32x2)
// ---------------------------------------------------------------------------
__global__ __launch_bounds__(256) void qkv_kernel(const float* __restrict__ x)
{
    __shared__ float sx[32*EMB_];
    int r0 = blockIdx.x * 32;
    {
        const float4* xin = (const float4*)(x + (size_t)r0*EMB_);
        float4* sx4 = (float4*)sx;
        for (int i = threadIdx.x; i < 2048; i += 256) sx4[i] = xin[i];
    }
    __syncthreads();

    int cg = threadIdx.x & 63, rg = threadIdx.x >> 6;
    ull acc[8][3];
#pragma unroll
    for (int rr = 0; rr < 8; rr++)
#pragma unroll
        for (int cc = 0; cc < 3; cc++) acc[rr][cc] = 0ull;

    ull wc[3], wn[3];
#pragma unroll
    for (int cc = 0; cc < 3; cc++)
        wc[cc] = *(const ull*)&g_wqp[cg + 64*cc];

    for (int kp = 0; kp < 128; kp++) {
        if (kp < 127) {
#pragma unroll
            for (int cc = 0; cc < 3; cc++)
                wn[cc] = *(const ull*)&g_wqp[(kp+1)*192 + cg + 64*cc];
        }
#pragma unroll
        for (int rr = 0; rr < 8; rr++) {
            ull a = *(const ull*)&sx[(rg*8+rr)*EMB_ + 2*kp];
            FMA2(acc[rr][0], a, wc[0]);
            FMA2(acc[rr][1], a, wc[1]);
            FMA2(acc[rr][2], a, wc[2]);
        }
#pragma unroll
        for (int cc = 0; cc < 3; cc++) wc[cc] = wn[cc];
    }
#pragma unroll
    for (int rr = 0; rr < 8; rr++) {
        float2 sq = unpk2(acc[rr][0]);
        float2 sk = unpk2(acc[rr][1]);
        float2 sv = unpk2(acc[rr][2]);
        int row = r0 + rg*8 + rr;
        g_qmk[row*64 + cg] = (sq.x + sq.y) - (sk.x + sk.y);
        g_v  [row*64 + cg] = sv.x + sv.y;
    }
}

// ---------------------------------------------------------------------------
// kNN: unchanged
// ---------------------------------------------------------------------------
__global__ __launch_bounds__(256) void knn_kernel(const float* __restrict__ pos)
{
    extern __shared__ float ksm[];
    float* sp = ksm;
    float* sd = ksm + 6144;
    int*   si = (int*)(ksm + 10240);

    int batch = blockIdx.x >> 5;
    int chunk = blockIdx.x & 31;
    const float* pb = pos + batch*N_*3;
    for (int e = threadIdx.x; e < N_*3; e += 256) sp[e] = pb[e];
    __syncthreads();

    int q = threadIdx.x >> 2;
    int s = threadIdx.x & 3;
    int qi = chunk*64 + q;
    float px = sp[qi*3+0], py = sp[qi*3+1], pz = sp[qi*3+2];

    float bd[KNN_]; int bi[KNN_];
#pragma unroll
    for (int t = 0; t < KNN_; t++) { bd[t] = 3.4e38f; bi[t] = 0; }

    int j0 = s * 512;
    for (int j = j0; j < j0 + 512; j++) {
        float dx = sp[j*3+0]-px, dy = sp[j*3+1]-py, dz = sp[j*3+2]-pz;
        float d2 = dx*dx + dy*dy + dz*dz;
        if (d2 < bd[KNN_-1]) {
            float cd = d2; int ci = j;
#pragma unroll
            for (int t = 0; t < KNN_; t++) {
                if (cd < bd[t]) {
                    float td = bd[t]; bd[t] = cd; cd = td;
                    int   ti = bi[t]; bi[t] = ci; ci = ti;
                }
            }
        }
    }
    int lb = (q*4 + s)*16;
#pragma unroll
    for (int t = 0; t < KNN_; t++) { sd[lb+t] = bd[t]; si[lb+t] = bi[t]; }
    __syncthreads();

    if (threadIdx.x < 64) {
        int qq = threadIdx.x;
        int p[4] = {0,0,0,0};
        int base = qq*64;
        int obase = (batch*N_ + chunk*64 + qq)*KNN_;
#pragma unroll
        for (int t = 0; t < KNN_; t++) {
            float best = sd[base + 0*16 + p[0]]; int bsel = 0;
            float c1 = sd[base + 1*16 + p[1]];
            if (c1 < best) { best = c1; bsel = 1; }
            float c2 = sd[base + 2*16 + p[2]];
            if (c2 < best) { best = c2; bsel = 2; }
            float c3 = sd[base + 3*16 + p[3]];
            if (c3 < best) { best = c3; bsel = 3; }
            g_idx[obase + t] = batch*N_ + si[base + bsel*16 + p[bsel]];
            p[bsel]++;
        }
    }
}

// ---------------------------------------------------------------------------
// Fused mma.sync kernel: 8 points/block, 8 warps (warp = point m-tile).
// smem: w1 frags 64KB | w2 frags 64KB | wp2 frags 16KB | misc ~7KB = 151KB
// ---------------------------------------------------------------------------
#define SMEM_FUSED_BYTES 154624

__global__ __launch_bounds__(256) void fused_kernel(
    const float* __restrict__ pos,
    const float* __restrict__ w_pos1, const float* __restrict__ b_pos1,
    const float* __restrict__ b_pos2,
    const float* __restrict__ b_att1, const float* __restrict__ b_att2,
    const float* __restrict__ w_out,  const float* __restrict__ b_out,
    float* __restrict__ out)
{
    extern __shared__ u32 smu[];
    u32* sW1F = smu;                 // 16384
    u32* sW2F = smu + 16384;         // 16384
    u32* sWPF = smu + 32768;         // 4096
    float* sF   = (float*)(smu + 36864);
    float* sRel = sF;                // 512
    float* sWP1 = sF + 512;          // 192
    float* sBp1 = sF + 704;          // 64
    float* sBp2 = sF + 768;          // 64
    float* sBa1 = sF + 832;          // 256
    float* sBa2 = sF + 1088;         // 64
    float* sAgg = sF + 1152;         // 512
    int*   sNbr = (int*)(sF + 1664); // 128

    const int tid  = threadIdx.x;
    const int wid  = tid >> 5;
    const int lane = tid & 31;
    const int gp0  = blockIdx.x * 8;

    // ---- staging ----
    {
        const uint4* s1 = (const uint4*)g_w1f;  uint4* d1 = (uint4*)sW1F;
        const uint4* s2 = (const uint4*)g_w2f;  uint4* d2 = (uint4*)sW2F;
        for (int i = tid; i < 4096; i += 256) { d1[i] = s1[i]; d2[i] = s2[i]; }
        const uint4* s3 = (const uint4*)g_wpf;  uint4* d3 = (uint4*)sWPF;
        for (int i = tid; i < 1024; i += 256) d3[i] = s3[i];
    }
    if (tid < 192) sWP1[tid] = w_pos1[tid];
    if (tid < 64) {
        sBp1[tid] = b_pos1[tid];
        sBp2[tid] = b_pos2[tid];
        sBa2[tid] = b_att2[tid];
    }
    sBa1[tid] = b_att1[tid];
    if (tid < 128) {
        int gp = gp0 + (tid >> 4);
        int nbr = g_idx[gp*KNN_ + (tid & 15)];
        sNbr[tid] = nbr;
        sRel[tid*4+0] = pos[nbr*3+0] - pos[gp*3+0];
        sRel[tid*4+1] = pos[nbr*3+1] - pos[gp*3+1];
        sRel[tid*4+2] = pos[nbr*3+2] - pos[gp*3+2];
    }
    __syncthreads();

    const int mt  = wid;            // point / m-tile
    const int g   = lane >> 2;
    const int tig = lane & 3;
    const int prA = mt*16 + g;      // pair-row A
    const int prB = prA + 8;        // pair-row B

    // ---- P1: mid = relu(rel @ wp1 + bp1) -> A-frags (regs) ----
    u32 midH[16], midL[16];
    {
        float rA0 = sRel[prA*4+0], rA1 = sRel[prA*4+1], rA2 = sRel[prA*4+2];
        float rB0 = sRel[prB*4+0], rB1 = sRel[prB*4+1], rB2 = sRel[prB*4+2];
#pragma unroll
        for (int kt = 0; kt < 4; kt++)
#pragma unroll
            for (int cb = 0; cb < 2; cb++) {
                int c0 = kt*16 + cb*8 + tig*2;
                float wx0 = sWP1[c0],   wy0 = sWP1[64+c0],   wz0 = sWP1[128+c0];
                float wx1 = sWP1[c0+1], wy1 = sWP1[64+c0+1], wz1 = sWP1[128+c0+1];
                float bb0 = sBp1[c0], bb1 = sBp1[c0+1];
                float a0 = fmaxf(rA0*wx0 + rA1*wy0 + rA2*wz0 + bb0, 0.f);
                float a1 = fmaxf(rA0*wx1 + rA1*wy1 + rA2*wz1 + bb1, 0.f);
                float b0 = fmaxf(rB0*wx0 + rB1*wy0 + rB2*wz0 + bb0, 0.f);
                float b1 = fmaxf(rB0*wx1 + rB1*wy1 + rB2*wz1 + bb1, 0.f);
                int r = kt*4 + cb*2;
                midH[r]   = pack_hi(a0, a1);  midL[r]   = pack_lo(a0, a1);
                midH[r+1] = pack_hi(b0, b1);  midL[r+1] = pack_lo(b0, b1);
            }
    }

    // ---- P2: rpe = mid @ wp2 (mma, split x3) ----
    float rpe[8][4];
#pragma unroll
    for (int nt = 0; nt < 8; nt++)
#pragma unroll
        for (int r = 0; r < 4; r++) rpe[nt][r] = 0.f;
#pragma unroll
    for (int kt = 0; kt < 4; kt++) {
#pragma unroll
        for (int nt = 0; nt < 8; nt++) {
            int idx = ((kt*8 + nt)*32 + lane)*2;
            uint2 bh = *(const uint2*)&sWPF[idx];
            uint2 bl = *(const uint2*)&sWPF[2048 + idx];
            mma_bf16(rpe[nt], &midH[kt*4], bh.x, bh.y);
            mma_bf16(rpe[nt], &midH[kt*4], bl.x, bl.y);
            mma_bf16(rpe[nt], &midL[kt*4], bh.x, bh.y);
        }
    }

    // ---- P2 epilogue: h frags (regs) + vn (regs) ----
    u32 hH[16], hL[16];
    float vnr[8][4];
    {
        int nA = sNbr[prA], nB = sNbr[prB];
#pragma unroll
        for (int nt = 0; nt < 8; nt++) {
            int c0 = nt*8 + tig*2;
            float b0 = sBp2[c0], b1 = sBp2[c0+1];
            float2 qA = *(const float2*)&g_qmk[nA*64 + c0];
            float2 qB = *(const float2*)&g_qmk[nB*64 + c0];
            float2 vA = *(const float2*)&g_v[nA*64 + c0];
            float2 vB = *(const float2*)&g_v[nB*64 + c0];
            float r0 = rpe[nt][0] + b0, r1 = rpe[nt][1] + b1;
            float r2 = rpe[nt][2] + b0, r3 = rpe[nt][3] + b1;
            vnr[nt][0] = vA.x + r0;  vnr[nt][1] = vA.y + r1;
            vnr[nt][2] = vB.x + r2;  vnr[nt][3] = vB.y + r3;
            int fr = (nt >> 1)*4 + (nt & 1)*2;
            float hA0 = qA.x + r0, hA1 = qA.y + r1;
            float hB0 = qB.x + r2, hB1 = qB.y + r3;
            hH[fr]   = pack_hi(hA0, hA1);  hL[fr]   = pack_lo(hA0, hA1);
            hH[fr+1] = pack_hi(hB0, hB1);  hL[fr+1] = pack_lo(hB0, hB1);
        }
    }

    // ---- MMA1 + epilogue + MMA2, chunked over t columns ----
    float sim[8][4];
#pragma unroll
    for (int nt = 0; nt < 8; nt++)
#pragma unroll
        for (int r = 0; r < 4; r++) sim[nt][r] = 0.f;

#pragma unroll
    for (int ch = 0; ch < 4; ch++) {
        float tacc[8][4];
#pragma unroll
        for (int nt = 0; nt < 8; nt++)
#pragma unroll
            for (int r = 0; r < 4; r++) tacc[nt][r] = 0.f;
#pragma unroll
        for (int kt = 0; kt < 4; kt++) {
#pragma unroll
            for (int nt = 0; nt < 8; nt++) {
                int idx = ((kt*32 + ch*8 + nt)*32 + lane)*2;
                uint2 bh = *(const uint2*)&sW1F[idx];
                uint2 bl = *(const uint2*)&sW1F[8192 + idx];
                mma_bf16(tacc[nt], &hH[kt*4], bh.x, bh.y);
                mma_bf16(tacc[nt], &hH[kt*4], bl.x, bl.y);
                mma_bf16(tacc[nt], &hL[kt*4], bh.x, bh.y);
            }
        }
        // epilogue: t = relu(tacc + ba1) -> A2 frags
        u32 tH[16], tL[16];
#pragma unroll
        for (int nt = 0; nt < 8; nt++) {
            int c0 = ch*64 + nt*8 + tig*2;
            float b0 = sBa1[c0], b1 = sBa1[c0+1];
            float t0 = fmaxf(tacc[nt][0] + b0, 0.f);
            float t1 = fmaxf(tacc[nt][1] + b1, 0.f);
            float t2 = fmaxf(tacc[nt][2] + b0, 0.f);
            float t3 = fmaxf(tacc[nt][3] + b1, 0.f);
            int fr = (nt >> 1)*4 + (nt & 1)*2;
            tH[fr]   = pack_hi(t0, t1);  tL[fr]   = pack_lo(t0, t1);
            tH[fr+1] = pack_hi(t2, t3);  tL[fr+1] = pack_lo(t2, t3);
        }
        // MMA2 partial over this chunk's K
#pragma unroll
        for (int kl = 0; kl < 4; kl++) {
            int kt2 = ch*4 + kl;
#pragma unroll
            for (int nt = 0; nt < 8; nt++) {
                int idx = ((kt2*8 + nt)*32 + lane)*2;
                uint2 bh = *(const uint2*)&sW2F[idx];
                uint2 bl = *(const uint2*)&sW2F[8192 + idx];
                mma_bf16(sim[nt], &tH[kl*4], bh.x, bh.y);
                mma_bf16(sim[nt], &tH[kl*4], bl.x, bl.y);
                mma_bf16(sim[nt], &tL[kl*4], bh.x, bh.y);
            }
        }
    }

    // ---- sim bias + softmax (rows A and B) ----
#pragma unroll
    for (int nt = 0; nt < 8; nt++) {
        int c0 = nt*8 + tig*2;
        float b0 = sBa2[c0], b1 = sBa2[c0+1];
        sim[nt][0] += b0; sim[nt][1] += b1;
        sim[nt][2] += b0; sim[nt][3] += b1;
    }
    {
        float mxA = -3.4e38f, mxB = -3.4e38f;
#pragma unroll
        for (int nt = 0; nt < 8; nt++) {
            mxA = fmaxf(mxA, fmaxf(sim[nt][0], sim[nt][1]));
            mxB = fmaxf(mxB, fmaxf(sim[nt][2], sim[nt][3]));
        }
        mxA = fmaxf(mxA, __shfl_xor_sync(0xffffffffu, mxA, 1));
        mxA = fmaxf(mxA, __shfl_xor_sync(0xffffffffu, mxA, 2));
        mxB = fmaxf(mxB, __shfl_xor_sync(0xffffffffu, mxB, 1));
        mxB = fmaxf(mxB, __shfl_xor_sync(0xffffffffu, mxB, 2));
        float sA = 0.f, sB = 0.f;
#pragma unroll
        for (int nt = 0; nt < 8; nt++) {
            sim[nt][0] = __expf(sim[nt][0] - mxA); sA += sim[nt][0];
            sim[nt][1] = __expf(sim[nt][1] - mxA); sA += sim[nt][1];
            sim[nt][2] = __expf(sim[nt][2] - mxB); sB += sim[nt][2];
            sim[nt][3] = __expf(sim[nt][3] - mxB); sB += sim[nt][3];
        }
        sA += __shfl_xor_sync(0xffffffffu, sA, 1);
        sA += __shfl_xor_sync(0xffffffffu, sA, 2);
        sB += __shfl_xor_sync(0xffffffffu, sB, 1);
        sB += __shfl_xor_sync(0xffffffffu, sB, 2);
        float iA = 1.f / sA, iB = 1.f / sB;
#pragma unroll
        for (int nt = 0; nt < 8; nt++) {
            sim[nt][0] *= iA; sim[nt][1] *= iA;
            sim[nt][2] *= iB; sim[nt][3] *= iB;
        }
    }

    // ---- channel norm over 16 neighbors + aggregate ----
#pragma unroll
    for (int nt = 0; nt < 8; nt++) {
#pragma unroll
        for (int p = 0; p < 2; p++) {
            float a0 = sim[nt][p], a1 = sim[nt][2+p];
            float s2 = a0*a0 + a1*a1;
            float dv = a0*vnr[nt][p] + a1*vnr[nt][2+p];
            s2 += __shfl_xor_sync(0xffffffffu, s2, 4);
            s2 += __shfl_xor_sync(0xffffffffu, s2, 8);
            s2 += __shfl_xor_sync(0xffffffffu, s2, 16);
            dv += __shfl_xor_sync(0xffffffffu, dv, 4);
            dv += __shfl_xor_sync(0xffffffffu, dv, 8);
            dv += __shfl_xor_sync(0xffffffffu, dv, 16);
            if (g == 0)
                sAgg[mt*64 + nt*8 + tig*2 + p] = dv / fmaxf(sqrtf(s2), 1e-12f);
        }
    }
    __syncthreads();

    // ---- P7: out = agg @ w_out + b_out ----
    {
        float acc[8];
        float bb = b_out[tid];
#pragma unroll
        for (int p = 0; p < 8; p++) acc[p] = bb;
        for (int k = 0; k < 64; k++) {
            float w = w_out[k*256 + tid];
#pragma unroll
            for (int p = 0; p < 8; p++)
                acc[p] += sAgg[p*64 + k] * w;
        }
#pragma unroll
        for (int p = 0; p < 8; p++)
            out[(gp0 + p)*256 + tid] = acc[p];
    }
}

// ---------------------------------------------------------------------------
extern "C" void kernel_launch(void* const* d_in, const int* in_sizes, int n_in,
                              void* d_out, int out_size)
{
    const float* x      = (const float*)d_in[0];
    const float* pos    = (const float*)d_in[1];
    const float* w_qkv  = (const float*)d_in[2];
    const float* w_pos1 = (const float*)d_in[3];
    const float* b_pos1 = (const float*)d_in[4];
    const float* w_pos2 = (const float*)d_in[5];
    const float* b_pos2 = (const float*)d_in[6];
    const float* w_att1 = (const float*)d_in[7];
    const float* b_att1 = (const float*)d_in[8];
    const float* w_att2 = (const float*)d_in[9];
    const float* b_att2 = (const float*)d_in[10];
    const float* w_out  = (const float*)d_in[11];
    const float* b_out  = (const float*)d_in[12];
    float* out = (float*)d_out;

    (void)in_sizes; (void)n_in; (void)out_size;

    cudaFuncSetAttribute(fused_kernel,
                         cudaFuncAttributeMaxDynamicSharedMemorySize, SMEM_FUSED_BYTES);
    const int smem_knn = (6144 + 4096 + 4096) * 4;
    cudaFuncSetAttribute(knn_kernel,
                         cudaFuncAttributeMaxDynamicSharedMemorySize, smem_knn);

    prep_kernel<<<240, 256>>>(w_qkv, w_att1, w_att2, w_pos2);
    qkv_kernel<<<NPTS_/32, 256>>>(x);
    knn_kernel<<<256, 256, smem_knn>>>(pos);
    fused_kernel<<<NPTS_/8, 256, SMEM_FUSED_BYTES>>>(
        pos, w_pos1, b_pos1, b_pos2, b_att1, b_att2, w_out, b_out, out);
}

// round 10
// speedup vs baseline: 1.8654x; 1.1128x over previous
#include <cuda_runtime.h>
#include <cuda_bf16.h>

#define B_    8
#define N_    2048
#define EMB_  256
#define KNN_  16
#define NPTS_ (B_*N_)

typedef unsigned long long ull;
typedef unsigned int u32;

// bf16 hi/lo split packers (lower col -> low 16 bits)
__device__ __forceinline__ u32 pack_hi(float v0, float v1) {
    __nv_bfloat162 h = __floats2bfloat162_rn(v0, v1);
    return *(u32*)&h;
}
__device__ __forceinline__ u32 pack_lo(float v0, float v1) {
    __nv_bfloat16 h0 = __float2bfloat16(v0), h1 = __float2bfloat16(v1);
    __nv_bfloat162 l = __floats2bfloat162_rn(v0 - __bfloat162float(h0),
                                             v1 - __bfloat162float(h1));
    return *(u32*)&l;
}

// m16n8k16 bf16 mma, f32 accum
__device__ __forceinline__ void mma_bf16(float d[4], const u32 a[4], u32 b0, u32 b1) {
    asm volatile("mma.sync.aligned.m16n8k16.row.col.f32.bf16.bf16.f32 "
        "{%0,%1,%2,%3}, {%4,%5,%6,%7}, {%8,%9}, {%0,%1,%2,%3};"
        : "+f"(d[0]), "+f"(d[1]), "+f"(d[2]), "+f"(d[3])
        : "r"(a[0]), "r"(a[1]), "r"(a[2]), "r"(a[3]), "r"(b0), "r"(b1));
}

// ---- Scratch (device globals) ----
__device__ float g_qmk[NPTS_*64];
__device__ float g_v  [NPTS_*64];
__device__ int   g_idx[NPTS_*KNN_];
// B-fragment-ordered weights, bf16 hi half then lo half:
__device__ __align__(16) u32 g_wqf[49152];        // w_qkv  [kt16][nt24][lane][b2] x2
__device__ __align__(16) u32 g_w1f[16384];        // w_att1 [kt4][nt32][lane][b2] x2
__device__ __align__(16) u32 g_w2f[16384];        // w_att2 [kt16][nt8][lane][b2] x2
__device__ __align__(16) u32 g_wpf[4096];         // w_pos2 [kt4][nt8][lane][b2] x2
// x as A-fragments (hi/lo): [mtile1024][kt16][lane32][r4]
__device__ __align__(16) u32 g_xfh[2097152];
__device__ __align__(16) u32 g_xfl[2097152];

// ---------------------------------------------------------------------------
__global__ __launch_bounds__(256) void prep_kernel(
    const float* __restrict__ wq, const float* __restrict__ w1,
    const float* __restrict__ w2, const float* __restrict__ wp)
{
    int i = blockIdx.x*256 + threadIdx.x;
    if (i < 49152) {
        int half = (i >= 24576);
        int j2 = half ? i - 24576 : i;     // FIXED: true modulo, 24576 not pow2
        int b = j2 & 1, lane = (j2 >> 1) & 31;
        int ktnt = j2 >> 6;            // 0..383
        int nt = ktnt % 24, kt = ktnt / 24;
        int tig = lane & 3, g = lane >> 2;
        int k0 = kt*16 + tig*2 + 8*b, n = nt*8 + g;
        float v0 = wq[k0*192 + n], v1 = wq[(k0+1)*192 + n];
        g_wqf[i] = half ? pack_lo(v0, v1) : pack_hi(v0, v1);
    } else if (i < 53248) {
        int j = i - 49152;               // wp2 frags, 4096 u32
        int half = j >> 11, j2 = j & 2047;
        int b = j2 & 1, lane = (j2 >> 1) & 31, nt = (j2 >> 6) & 7, kt = j2 >> 9;
        int tig = lane & 3, g = lane >> 2;
        int k0 = kt*16 + tig*2 + 8*b, n = nt*8 + g;
        float v0 = wp[k0*64 + n], v1 = wp[(k0+1)*64 + n];
        g_wpf[j] = half ? pack_lo(v0, v1) : pack_hi(v0, v1);
    } else if (i < 69632) {
        int j = i - 53248;               // w1 frags, 16384 u32
        int half = j >> 13, j2 = j & 8191;
        int b = j2 & 1, lane = (j2 >> 1) & 31, nt = (j2 >> 6) & 31, kt = j2 >> 11;
        int tig = lane & 3, g = lane >> 2;
        int k0 = kt*16 + tig*2 + 8*b, n = nt*8 + g;
        float v0 = w1[k0*256 + n], v1 = w1[(k0+1)*256 + n];
        g_w1f[j] = half ? pack_lo(v0, v1) : pack_hi(v0, v1);
    } else if (i < 86016) {
        int j = i - 69632;               // w2 frags, 16384 u32
        int half = j >> 13, j2 = j & 8191;
        int b = j2 & 1, lane = (j2 >> 1) & 31, nt = (j2 >> 6) & 7, kt = j2 >> 9;
        int tig = lane & 3, g = lane >> 2;
        int k0 = kt*16 + tig*2 + 8*b, n = nt*8 + g;
        float v0 = w2[k0*64 + n], v1 = w2[(k0+1)*64 + n];
        g_w2f[j] = half ? pack_lo(v0, v1) : pack_hi(v0, v1);
    }
}

// ---------------------------------------------------------------------------
// xfrag: convert x -> bf16 hi/lo A-fragments.
// j = ((m*16 + kt)*32 + lane)*4 + r ; r: {(g,klo),(g+8,klo),(g,khi),(g+8,khi)}
// ---------------------------------------------------------------------------
__global__ __launch_bounds__(256) void xfrag_kernel(const float* __restrict__ x)
{
    int j = blockIdx.x*256 + threadIdx.x;     // < 2097152
    int r = j & 3;
    int lane = (j >> 2) & 31;
    int kt = (j >> 7) & 15;
    int m  = j >> 11;
    int g = lane >> 2, tig = lane & 3;
    int row = m*16 + (r & 1)*8 + g;
    int k   = kt*16 + (r >> 1)*8 + tig*2;
    float2 xv = *(const float2*)&x[row*256 + k];
    g_xfh[j] = pack_hi(xv.x, xv.y);
    g_xfl[j] = pack_lo(xv.x, xv.y);
}

// ---------------------------------------------------------------------------
// qkv via mma: 4 warps/block, warp = one 16-row m-tile; grid 256.
// acc[24][4]: n-tiles 0-7 = q, 8-15 = k, 16-23 = v.
// ---------------------------------------------------------------------------
__global__ __launch_bounds__(128) void qkv_mma_kernel()
{
    int wid = threadIdx.x >> 5, lane = threadIdx.x & 31;
    int mt = blockIdx.x*4 + wid;              // 0..1023
    int g = lane >> 2, tig = lane & 3;

    float acc[24][4];
#pragma unroll
    for (int nt = 0; nt < 24; nt++)
#pragma unroll
        for (int r = 0; r < 4; r++) acc[nt][r] = 0.f;

#pragma unroll 4
    for (int kt = 0; kt < 16; kt++) {
        int abase = ((mt*16 + kt)*32 + lane)*4;
        uint4 ah4 = *(const uint4*)&g_xfh[abase];
        uint4 al4 = *(const uint4*)&g_xfl[abase];
        u32 ah[4] = {ah4.x, ah4.y, ah4.z, ah4.w};
        u32 al[4] = {al4.x, al4.y, al4.z, al4.w};
#pragma unroll
        for (int nt = 0; nt < 24; nt++) {
            int idx = ((kt*24 + nt)*32 + lane)*2;
            uint2 bh = *(const uint2*)&g_wqf[idx];
            uint2 bl = *(const uint2*)&g_wqf[24576 + idx];
            mma_bf16(acc[nt], ah, bh.x, bh.y);
            mma_bf16(acc[nt], ah, bl.x, bl.y);
            mma_bf16(acc[nt], al, bh.x, bh.y);
        }
    }

    int row0 = mt*16 + g;
#pragma unroll
    for (int nt = 0; nt < 8; nt++) {
        int c = nt*8 + tig*2;
        float2 qa = make_float2(acc[nt][0] - acc[nt+8][0], acc[nt][1] - acc[nt+8][1]);
        float2 qb = make_float2(acc[nt][2] - acc[nt+8][2], acc[nt][3] - acc[nt+8][3]);
        *(float2*)&g_qmk[row0*64 + c]     = qa;
        *(float2*)&g_qmk[(row0+8)*64 + c] = qb;
        *(float2*)&g_v[row0*64 + c]     = make_float2(acc[nt+16][0], acc[nt+16][1]);
        *(float2*)&g_v[(row0+8)*64 + c] = make_float2(acc[nt+16][2], acc[nt+16][3]);
    }
}

// ---------------------------------------------------------------------------
// kNN: unchanged
// ---------------------------------------------------------------------------
__global__ __launch_bounds__(256) void knn_kernel(const float* __restrict__ pos)
{
    extern __shared__ float ksm[];
    float* sp = ksm;
    float* sd = ksm + 6144;
    int*   si = (int*)(ksm + 10240);

    int batch = blockIdx.x >> 5;
    int chunk = blockIdx.x & 31;
    const float* pb = pos + batch*N_*3;
    for (int e = threadIdx.x; e < N_*3; e += 256) sp[e] = pb[e];
    __syncthreads();

    int q = threadIdx.x >> 2;
    int s = threadIdx.x & 3;
    int qi = chunk*64 + q;
    float px = sp[qi*3+0], py = sp[qi*3+1], pz = sp[qi*3+2];

    float bd[KNN_]; int bi[KNN_];
#pragma unroll
    for (int t = 0; t < KNN_; t++) { bd[t] = 3.4e38f; bi[t] = 0; }

    int j0 = s * 512;
    for (int j = j0; j < j0 + 512; j++) {
        float dx = sp[j*3+0]-px, dy = sp[j*3+1]-py, dz = sp[j*3+2]-pz;
        float d2 = dx*dx + dy*dy + dz*dz;
        if (d2 < bd[KNN_-1]) {
            float cd = d2; int ci = j;
#pragma unroll
            for (int t = 0; t < KNN_; t++) {
                if (cd < bd[t]) {
                    float td = bd[t]; bd[t] = cd; cd = td;
                    int   ti = bi[t]; bi[t] = ci; ci = ti;
                }
            }
        }
    }
    int lb = (q*4 + s)*16;
#pragma unroll
    for (int t = 0; t < KNN_; t++) { sd[lb+t] = bd[t]; si[lb+t] = bi[t]; }
    __syncthreads();

    if (threadIdx.x < 64) {
        int qq = threadIdx.x;
        int p[4] = {0,0,0,0};
        int base = qq*64;
        int obase = (batch*N_ + chunk*64 + qq)*KNN_;
#pragma unroll
        for (int t = 0; t < KNN_; t++) {
            float best = sd[base + 0*16 + p[0]]; int bsel = 0;
            float c1 = sd[base + 1*16 + p[1]];
            if (c1 < best) { best = c1; bsel = 1; }
            float c2 = sd[base + 2*16 + p[2]];
            if (c2 < best) { best = c2; bsel = 2; }
            float c3 = sd[base + 3*16 + p[3]];
            if (c3 < best) { best = c3; bsel = 3; }
            g_idx[obase + t] = batch*N_ + si[base + bsel*16 + p[bsel]];
            p[bsel]++;
        }
    }
}

// ---------------------------------------------------------------------------
// Fused mma.sync kernel: 12 points/block, 12 warps (warp = point m-tile).
// ---------------------------------------------------------------------------
#define PPB 12
#define SMEM_FUSED_BYTES 156928

__global__ __launch_bounds__(384) void fused_kernel(
    const float* __restrict__ pos,
    const float* __restrict__ w_pos1, const float* __restrict__ b_pos1,
    const float* __restrict__ b_pos2,
    const float* __restrict__ b_att1, const float* __restrict__ b_att2,
    const float* __restrict__ w_out,  const float* __restrict__ b_out,
    float* __restrict__ out)
{
    extern __shared__ u32 smu[];
    u32* sW1F = smu;                 // 16384
    u32* sW2F = smu + 16384;         // 16384
    u32* sWPF = smu + 32768;         // 4096
    float* sF   = (float*)(smu + 36864);
    float* sRel = sF;                // 768 (192 x 4)
    float* sWP1 = sF + 768;          // 192
    float* sBp1 = sF + 960;          // 64
    float* sBp2 = sF + 1024;         // 64
    float* sBa1 = sF + 1088;         // 256
    float* sBa2 = sF + 1344;         // 64
    float* sAgg = sF + 1408;         // 768
    int*   sNbr = (int*)(sF + 2176); // 192

    const int tid  = threadIdx.x;
    const int wid  = tid >> 5;
    const int lane = tid & 31;
    const int gp0  = blockIdx.x * PPB;

    // ---- staging ----
    {
        const uint4* s1 = (const uint4*)g_w1f;  uint4* d1 = (uint4*)sW1F;
        const uint4* s2 = (const uint4*)g_w2f;  uint4* d2 = (uint4*)sW2F;
        for (int i = tid; i < 4096; i += 384) { d1[i] = s1[i]; d2[i] = s2[i]; }
        const uint4* s3 = (const uint4*)g_wpf;  uint4* d3 = (uint4*)sWPF;
        for (int i = tid; i < 1024; i += 384) d3[i] = s3[i];
    }
    if (tid < 192) sWP1[tid] = w_pos1[tid];
    if (tid < 64) {
        sBp1[tid] = b_pos1[tid];
        sBp2[tid] = b_pos2[tid];
        sBa2[tid] = b_att2[tid];
    }
    if (tid < 256) sBa1[tid] = b_att1[tid];
    if (tid < 16*PPB) {
        int gp = gp0 + (tid >> 4);
        if (gp >= NPTS_) gp = NPTS_ - 1;           // clamp (tail block)
        int nbr = g_idx[gp*KNN_ + (tid & 15)];
        sNbr[tid] = nbr;
        sRel[tid*4+0] = pos[nbr*3+0] - pos[gp*3+0];
        sRel[tid*4+1] = pos[nbr*3+1] - pos[gp*3+1];
        sRel[tid*4+2] = pos[nbr*3+2] - pos[gp*3+2];
    }
    __syncthreads();

    const int mt  = wid;            // point / m-tile (0..11)
    const int g   = lane >> 2;
    const int tig = lane & 3;
    const int prA = mt*16 + g;      // pair-row A
    const int prB = prA + 8;        // pair-row B

    // ---- P1: mid = relu(rel @ wp1 + bp1) -> A-frags (regs) ----
    u32 midH[16], midL[16];
    {
        float rA0 = sRel[prA*4+0], rA1 = sRel[prA*4+1], rA2 = sRel[prA*4+2];
        float rB0 = sRel[prB*4+0], rB1 = sRel[prB*4+1], rB2 = sRel[prB*4+2];
#pragma unroll
        for (int kt = 0; kt < 4; kt++)
#pragma unroll
            for (int cb = 0; cb < 2; cb++) {
                int c0 = kt*16 + cb*8 + tig*2;
                float wx0 = sWP1[c0],   wy0 = sWP1[64+c0],   wz0 = sWP1[128+c0];
                float wx1 = sWP1[c0+1], wy1 = sWP1[64+c0+1], wz1 = sWP1[128+c0+1];
                float bb0 = sBp1[c0], bb1 = sBp1[c0+1];
                float a0 = fmaxf(rA0*wx0 + rA1*wy0 + rA2*wz0 + bb0, 0.f);
                float a1 = fmaxf(rA0*wx1 + rA1*wy1 + rA2*wz1 + bb1, 0.f);
                float b0 = fmaxf(rB0*wx0 + rB1*wy0 + rB2*wz0 + bb0, 0.f);
                float b1 = fmaxf(rB0*wx1 + rB1*wy1 + rB2*wz1 + bb1, 0.f);
                int r = kt*4 + cb*2;
                midH[r]   = pack_hi(a0, a1);  midL[r]   = pack_lo(a0, a1);
                midH[r+1] = pack_hi(b0, b1);  midL[r+1] = pack_lo(b0, b1);
            }
    }

    // ---- P2: rpe = mid @ wp2 (mma, split x3) ----
    float rpe[8][4];
#pragma unroll
    for (int nt = 0; nt < 8; nt++)
#pragma unroll
        for (int r = 0; r < 4; r++) rpe[nt][r] = 0.f;
#pragma unroll
    for (int kt = 0; kt < 4; kt++) {
#pragma unroll
        for (int nt = 0; nt < 8; nt++) {
            int idx = ((kt*8 + nt)*32 + lane)*2;
            uint2 bh = *(const uint2*)&sWPF[idx];
            uint2 bl = *(const uint2*)&sWPF[2048 + idx];
            mma_bf16(rpe[nt], &midH[kt*4], bh.x, bh.y);
            mma_bf16(rpe[nt], &midH[kt*4], bl.x, bl.y);
            mma_bf16(rpe[nt], &midL[kt*4], bh.x, bh.y);
        }
    }

    // ---- P2 epilogue: h frags (regs) + vn (regs) ----
    u32 hH[16], hL[16];
    float vnr[8][4];
    {
        int nA = sNbr[prA], nB = sNbr[prB];
#pragma unroll
        for (int nt = 0; nt < 8; nt++) {
            int c0 = nt*8 + tig*2;
            float b0 = sBp2[c0], b1 = sBp2[c0+1];
            float2 qA = *(const float2*)&g_qmk[nA*64 + c0];
            float2 qB = *(const float2*)&g_qmk[nB*64 + c0];
            float2 vA = *(const float2*)&g_v[nA*64 + c0];
            float2 vB = *(const float2*)&g_v[nB*64 + c0];
            float r0 = rpe[nt][0] + b0, r1 = rpe[nt][1] + b1;
            float r2 = rpe[nt][2] + b0, r3 = rpe[nt][3] + b1;
            vnr[nt][0] = vA.x + r0;  vnr[nt][1] = vA.y + r1;
            vnr[nt][2] = vB.x + r2;  vnr[nt][3] = vB.y + r3;
            int fr = (nt >> 1)*4 + (nt & 1)*2;
            float hA0 = qA.x + r0, hA1 = qA.y + r1;
            float hB0 = qB.x + r2, hB1 = qB.y + r3;
            hH[fr]   = pack_hi(hA0, hA1);  hL[fr]   = pack_lo(hA0, hA1);
            hH[fr+1] = pack_hi(hB0, hB1);  hL[fr+1] = pack_lo(hB0, hB1);
        }
    }

    // ---- MMA1 + epilogue + MMA2, chunked over t columns ----
    float sim[8][4];
#pragma unroll
    for (int nt = 0; nt < 8; nt++)
#pragma unroll
        for (int r = 0; r < 4; r++) sim[nt][r] = 0.f;

#pragma unroll
    for (int ch = 0; ch < 4; ch++) {
        float tacc[8][4];
#pragma unroll
        for (int nt = 0; nt < 8; nt++)
#pragma unroll
            for (int r = 0; r < 4; r++) tacc[nt][r] = 0.f;
#pragma unroll
        for (int kt = 0; kt < 4; kt++) {
#pragma unroll
            for (int nt = 0; nt < 8; nt++) {
                int idx = ((kt*32 + ch*8 + nt)*32 + lane)*2;
                uint2 bh = *(const uint2*)&sW1F[idx];
                uint2 bl = *(const uint2*)&sW1F[8192 + idx];
                mma_bf16(tacc[nt], &hH[kt*4], bh.x, bh.y);
                mma_bf16(tacc[nt], &hH[kt*4], bl.x, bl.y);
                mma_bf16(tacc[nt], &hL[kt*4], bh.x, bh.y);
            }
        }
        // epilogue: t = relu(tacc + ba1) -> A2 frags
        u32 tH[16], tL[16];
#pragma unroll
        for (int nt = 0; nt < 8; nt++) {
            int c0 = ch*64 + nt*8 + tig*2;
            float b0 = sBa1[c0], b1 = sBa1[c0+1];
            float t0 = fmaxf(tacc[nt][0] + b0, 0.f);
            float t1 = fmaxf(tacc[nt][1] + b1, 0.f);
            float t2 = fmaxf(tacc[nt][2] + b0, 0.f);
            float t3 = fmaxf(tacc[nt][3] + b1, 0.f);
            int fr = (nt >> 1)*4 + (nt & 1)*2;
            tH[fr]   = pack_hi(t0, t1);  tL[fr]   = pack_lo(t0, t1);
            tH[fr+1] = pack_hi(t2, t3);  tL[fr+1] = pack_lo(t2, t3);
        }
        // MMA2 partial over this chunk's K
#pragma unroll
        for (int kl = 0; kl < 4; kl++) {
            int kt2 = ch*4 + kl;
#pragma unroll
            for (int nt = 0; nt < 8; nt++) {
                int idx = ((kt2*8 + nt)*32 + lane)*2;
                uint2 bh = *(const uint2*)&sW2F[idx];
                uint2 bl = *(const uint2*)&sW2F[8192 + idx];
                mma_bf16(sim[nt], &tH[kl*4], bh.x, bh.y);
                mma_bf16(sim[nt], &tH[kl*4], bl.x, bl.y);
                mma_bf16(sim[nt], &tL[kl*4], bh.x, bh.y);
            }
        }
    }

    // ---- sim bias + softmax (rows A and B) ----
#pragma unroll
    for (int nt = 0; nt < 8; nt++) {
        int c0 = nt*8 + tig*2;
        float b0 = sBa2[c0], b1 = sBa2[c0+1];
        sim[nt][0] += b0; sim[nt][1] += b1;
        sim[nt][2] += b0; sim[nt][3] += b1;
    }
    {
        float mxA = -3.4e38f, mxB = -3.4e38f;
#pragma unroll
        for (int nt = 0; nt < 8; nt++) {
            mxA = fmaxf(mxA, fmaxf(sim[nt][0], sim[nt][1]));
            mxB = fmaxf(mxB, fmaxf(sim[nt][2], sim[nt][3]));
        }
        mxA = fmaxf(mxA, __shfl_xor_sync(0xffffffffu, mxA, 1));
        mxA = fmaxf(mxA, __shfl_xor_sync(0xffffffffu, mxA, 2));
        mxB = fmaxf(mxB, __shfl_xor_sync(0xffffffffu, mxB, 1));
        mxB = fmaxf(mxB, __shfl_xor_sync(0xffffffffu, mxB, 2));
        float sA = 0.f, sB = 0.f;
#pragma unroll
        for (int nt = 0; nt < 8; nt++) {
            sim[nt][0] = __expf(sim[nt][0] - mxA); sA += sim[nt][0];
            sim[nt][1] = __expf(sim[nt][1] - mxA); sA += sim[nt][1];
            sim[nt][2] = __expf(sim[nt][2] - mxB); sB += sim[nt][2];
            sim[nt][3] = __expf(sim[nt][3] - mxB); sB += sim[nt][3];
        }
        sA += __shfl_xor_sync(0xffffffffu, sA, 1);
        sA += __shfl_xor_sync(0xffffffffu, sA, 2);
        sB += __shfl_xor_sync(0xffffffffu, sB, 1);
        sB += __shfl_xor_sync(0xffffffffu, sB, 2);
        float iA = 1.f / sA, iB = 1.f / sB;
#pragma unroll
        for (int nt = 0; nt < 8; nt++) {
            sim[nt][0] *= iA; sim[nt][1] *= iA;
            sim[nt][2] *= iB; sim[nt][3] *= iB;
        }
    }

    // ---- channel norm over 16 neighbors + aggregate ----
#pragma unroll
    for (int nt = 0; nt < 8; nt++) {
#pragma unroll
        for (int p = 0; p < 2; p++) {
            float a0 = sim[nt][p], a1 = sim[nt][2+p];
            float s2 = a0*a0 + a1*a1;
            float dv = a0*vnr[nt][p] + a1*vnr[nt][2+p];
            s2 += __shfl_xor_sync(0xffffffffu, s2, 4);
            s2 += __shfl_xor_sync(0xffffffffu, s2, 8);
            s2 += __shfl_xor_sync(0xffffffffu, s2, 16);
            dv += __shfl_xor_sync(0xffffffffu, dv, 4);
            dv += __shfl_xor_sync(0xffffffffu, dv, 8);
            dv += __shfl_xor_sync(0xffffffffu, dv, 16);
            if (g == 0)
                sAgg[mt*64 + nt*8 + tig*2 + p] = dv / fmaxf(sqrtf(s2), 1e-12f);
        }
    }
    __syncthreads();

    // ---- P7: out = agg @ w_out + b_out ----
    if (tid < 256) {
        float acc[PPB];
        float bb = b_out[tid];
#pragma unroll
        for (int p = 0; p < PPB; p++) acc[p] = bb;
        for (int k = 0; k < 64; k++) {
            float w = w_out[k*256 + tid];
#pragma unroll
            for (int p = 0; p < PPB; p++)
                acc[p] += sAgg[p*64 + k] * w;
        }
#pragma unroll
        for (int p = 0; p < PPB; p++)
            if (gp0 + p < NPTS_)
                out[(gp0 + p)*256 + tid] = acc[p];
    }
}

// ---------------------------------------------------------------------------
extern "C" void kernel_launch(void* const* d_in, const int* in_sizes, int n_in,
                              void* d_out, int out_size)
{
    const float* x      = (const float*)d_in[0];
    const float* pos    = (const float*)d_in[1];
    const float* w_qkv  = (const float*)d_in[2];
    const float* w_pos1 = (const float*)d_in[3];
    const float* b_pos1 = (const float*)d_in[4];
    const float* w_pos2 = (const float*)d_in[5];
    const float* b_pos2 = (const float*)d_in[6];
    const float* w_att1 = (const float*)d_in[7];
    const float* b_att1 = (const float*)d_in[8];
    const float* w_att2 = (const float*)d_in[9];
    const float* b_att2 = (const float*)d_in[10];
    const float* w_out  = (const float*)d_in[11];
    const float* b_out  = (const float*)d_in[12];
    float* out = (float*)d_out;

    (void)in_sizes; (void)n_in; (void)out_size;

    cudaFuncSetAttribute(fused_kernel,
                         cudaFuncAttributeMaxDynamicSharedMemorySize, SMEM_FUSED_BYTES);
    const int smem_knn = (6144 + 4096 + 4096) * 4;
    cudaFuncSetAttribute(knn_kernel,
                         cudaFuncAttributeMaxDynamicSharedMemorySize, smem_knn);

    prep_kernel<<<336, 256>>>(w_qkv, w_att1, w_att2, w_pos2);
    xfrag_kernel<<<8192, 256>>>(x);
    qkv_mma_kernel<<<256, 128>>>();
    knn_kernel<<<256, 256, smem_knn>>>(pos);
    fused_kernel<<<(NPTS_ + PPB - 1)/PPB, 384, SMEM_FUSED_BYTES>>>(
        pos, w_pos1, b_pos1, b_pos2, b_att1, b_att2, w_out, b_out, out);
}